// round 13
// baseline (speedup 1.0000x reference)
#include <cuda_runtime.h>
#include <cstddef>
#include <cstdint>

#define T_   512
#define B_   64
#define E_   300
#define H_   512
#define L_   5
#define G3H_ 1536
#define NBLK   128    // fused recurrence: 64 ug x 2 bg
#define NTHR_R 384
#define GRPSZ  64     // CTAs per batch-group barrier

typedef unsigned long long ull;

// ---------------- scratch (no allocations allowed) ----------------
__device__ float g_xp0[(size_t)T_ * B_ * G3H_];   // 201 MB (layer0 input projection)
__device__ float g_hgY[2 * 2 * 512 * 32];         // y ring: [buf][bg][k][b32]
__device__ float g_hgZ[2 * 2 * 512 * 32];         // z ring: [buf][bg][k][b32]
__device__ float g_pooledp[2 * T_ * H_];          // per-bg partial sums
__device__ unsigned int g_arrive2[2 * 32];        // one counter per bg, 128B apart

__global__ void init_kernel() {
    if (threadIdx.x < 2 * 32) g_arrive2[threadIdx.x] = 0u;
}

// ---------------- f32x2 helpers (FFMA2 only reachable via PTX) ----------------
__device__ __forceinline__ ull ffma2(ull a, ull b, ull c) {
    ull d;
    asm("fma.rn.f32x2 %0, %1, %2, %3;" : "=l"(d) : "l"(a), "l"(b), "l"(c));
    return d;
}
__device__ __forceinline__ ull pack2(float lo, float hi) {
    ull d;
    asm("mov.b64 %0, {%1, %2};" : "=l"(d) : "f"(lo), "f"(hi));
    return d;
}
__device__ __forceinline__ float2 unpack2(ull v) {
    float2 r;
    asm("mov.b64 {%0, %1}, %2;" : "=f"(r.x), "=f"(r.y) : "l"(v));
    return r;
}
__device__ __forceinline__ uint32_t smem_u32(const void* p) {
    uint32_t a;
    asm("{ .reg .u64 t; cvta.to.shared.u64 t, %1; cvt.u32.u64 %0, t; }" : "=r"(a) : "l"(p));
    return a;
}
__device__ __forceinline__ void cp_async16(uint32_t dst, const void* src) {
    asm volatile("cp.async.cg.shared.global [%0], [%1], 16;" :: "r"(dst), "l"(src));
}

// ---------------- per-group barrier (64 co-resident CTAs sharing one bg) ----------------
__device__ __forceinline__ void group_barrier(unsigned int* epoch, unsigned int* cnt) {
    __syncthreads();
    if (threadIdx.x == 0) {
        __threadfence();
        unsigned int target = (*epoch + 1u) * GRPSZ;
        atomicAdd(cnt, 1u);
        while (*((volatile unsigned int*)cnt) < target) { }
        __threadfence();
    }
    __syncthreads();
    ++(*epoch);
}

// ---------------- fp32 GEMM: C[M,N] = A[M,K] @ W[N,K]^T + bias (R7, unchanged) ----------------
__global__ void __launch_bounds__(256, 2) gemm_kernel(
    const float* __restrict__ A, const int* __restrict__ gather,
    const float* __restrict__ W, const float* __restrict__ bias,
    float* __restrict__ C, int M, int N, int K)
{
    __shared__ __align__(16) float As[32][130];
    __shared__ __align__(16) float Ws[32][68];

    const int tid = threadIdx.x;
    const int tx = tid & 15;
    const int ty = tid >> 4;
    const int m0 = blockIdx.y * 128;
    const int n0 = blockIdx.x * 64;

    const int sq = tid & 7;
    const int sr = tid >> 3;

    const float* arow[4];
    #pragma unroll
    for (int r = 0; r < 4; ++r) {
        int am = m0 + sr + 32 * r;
        if (gather) am = gather[am];
        arow[r] = A + (size_t)am * K;
    }
    const float* wrow[2];
    #pragma unroll
    for (int r = 0; r < 2; ++r)
        wrow[r] = W + (size_t)(n0 + sr + 32 * r) * K;

    ull acc[4][4];
    #pragma unroll
    for (int mp = 0; mp < 4; ++mp)
        #pragma unroll
        for (int n = 0; n < 4; ++n) acc[mp][n] = 0ull;

    const int Kiter = (K + 31) >> 5;

    float4 pa[4], pw[2];
    {
        int k = sq * 4;
        #pragma unroll
        for (int r = 0; r < 4; ++r) {
            if (k + 3 < K) pa[r] = *(const float4*)(arow[r] + k);
            else {
                float4 z = {0.f,0.f,0.f,0.f};
                #pragma unroll
                for (int j = 0; j < 4; ++j) if (k + j < K) ((float*)&z)[j] = arow[r][k + j];
                pa[r] = z;
            }
        }
        #pragma unroll
        for (int r = 0; r < 2; ++r) {
            if (k + 3 < K) pw[r] = *(const float4*)(wrow[r] + k);
            else {
                float4 z = {0.f,0.f,0.f,0.f};
                #pragma unroll
                for (int j = 0; j < 4; ++j) if (k + j < K) ((float*)&z)[j] = wrow[r][k + j];
                pw[r] = z;
            }
        }
    }

    for (int ki = 0; ki < Kiter; ++ki) {
        #pragma unroll
        for (int r = 0; r < 4; ++r) {
            int mm = sr + 32 * r;
            As[sq * 4 + 0][mm] = pa[r].x;
            As[sq * 4 + 1][mm] = pa[r].y;
            As[sq * 4 + 2][mm] = pa[r].z;
            As[sq * 4 + 3][mm] = pa[r].w;
        }
        #pragma unroll
        for (int r = 0; r < 2; ++r) {
            int nn = sr + 32 * r;
            Ws[sq * 4 + 0][nn] = pw[r].x;
            Ws[sq * 4 + 1][nn] = pw[r].y;
            Ws[sq * 4 + 2][nn] = pw[r].z;
            Ws[sq * 4 + 3][nn] = pw[r].w;
        }
        __syncthreads();

        if (ki + 1 < Kiter) {
            int k = (ki + 1) * 32 + sq * 4;
            #pragma unroll
            for (int r = 0; r < 4; ++r) {
                if (k + 3 < K) pa[r] = *(const float4*)(arow[r] + k);
                else {
                    float4 z = {0.f,0.f,0.f,0.f};
                    #pragma unroll
                    for (int j = 0; j < 4; ++j) if (k + j < K) ((float*)&z)[j] = arow[r][k + j];
                    pa[r] = z;
                }
            }
            #pragma unroll
            for (int r = 0; r < 2; ++r) {
                if (k + 3 < K) pw[r] = *(const float4*)(wrow[r] + k);
                else {
                    float4 z = {0.f,0.f,0.f,0.f};
                    #pragma unroll
                    for (int j = 0; j < 4; ++j) if (k + j < K) ((float*)&z)[j] = wrow[r][k + j];
                    pw[r] = z;
                }
            }
        }

        #pragma unroll
        for (int kk = 0; kk < 32; ++kk) {
            ull a[4];
            a[0] = *(const ull*)&As[kk][ty * 8 + 0];
            a[1] = *(const ull*)&As[kk][ty * 8 + 2];
            a[2] = *(const ull*)&As[kk][ty * 8 + 4];
            a[3] = *(const ull*)&As[kk][ty * 8 + 6];
            float4 wv = *(const float4*)&Ws[kk][tx * 4];
            ull w[4];
            w[0] = pack2(wv.x, wv.x);
            w[1] = pack2(wv.y, wv.y);
            w[2] = pack2(wv.z, wv.z);
            w[3] = pack2(wv.w, wv.w);
            #pragma unroll
            for (int mp = 0; mp < 4; ++mp)
                #pragma unroll
                for (int n = 0; n < 4; ++n)
                    acc[mp][n] = ffma2(a[mp], w[n], acc[mp][n]);
        }
        __syncthreads();
    }

    float bs[4];
    #pragma unroll
    for (int n = 0; n < 4; ++n) bs[n] = bias[n0 + tx * 4 + n];

    #pragma unroll
    for (int mp = 0; mp < 4; ++mp) {
        float2 v[4];
        #pragma unroll
        for (int n = 0; n < 4; ++n) v[n] = unpack2(acc[mp][n]);
        size_t r0 = (size_t)(m0 + ty * 8 + mp * 2 + 0) * N + n0 + tx * 4;
        size_t r1 = (size_t)(m0 + ty * 8 + mp * 2 + 1) * N + n0 + tx * 4;
        float4 o;
        o.x = v[0].x + bs[0]; o.y = v[1].x + bs[1]; o.z = v[2].x + bs[2]; o.w = v[3].x + bs[3];
        *(float4*)&C[r0] = o;
        o.x = v[0].y + bs[0]; o.y = v[1].y + bs[1]; o.z = v[2].y + bs[2]; o.w = v[3].y + bs[3];
        *(float4*)&C[r1] = o;
    }
}

// ---------------- FUSED two-layer GRU wavefront ----------------
// 128 CTAs = 64 ug x 2 bg; CTA owns 8 units x 32 batches for BOTH layers.
// Tick t: y[t] = GRU0(xp0[t], y[t-1]) and z[t-1] = GRU1(Wih1 y[t-1], z[t-2]).
// 12 compute warps = 3 matrices (Whh0, Wih1, Whh1) x 4 pair-groups; thread =
// (lane=batch) x 3 row-pairs, full-k accumulation (no cross-warp reduction).
// W stored k-major transposed: wt2[(m*12+p)*1024 + k*2 + h] -> LDS.128 = 2 k's.

#define RS_WT    0            // 147456 B
#define RS_HY    147456       // [ring2][128k][32b] = 32768 B
#define RS_HZ    180224       // 32768 B
#define RS_RED   212992       // [36 pairs][32 b] ull = 9216 B
#define RS_XPS   222208       // [3g][8u][32b] = 3072 B
#define RS_TOTAL 225280

__global__ void __launch_bounds__(NTHR_R, 1) fused_gru_kernel(
    const float* __restrict__ xp0,
    const float* __restrict__ Whh0, const float* __restrict__ bhh0,
    const float* __restrict__ Wih1, const float* __restrict__ bih1,
    const float* __restrict__ Whh1, const float* __restrict__ bhh1,
    float* __restrict__ hgY, float* __restrict__ hgZ,
    float* __restrict__ pooledp)
{
    extern __shared__ char smem_raw[];
    float* wt2  = (float*)(smem_raw + RS_WT);
    float* hy_s = (float*)(smem_raw + RS_HY);
    float* hz_s = (float*)(smem_raw + RS_HZ);
    ull*   red  = (ull*)  (smem_raw + RS_RED);
    float* xps  = (float*)(smem_raw + RS_XPS);

    const int tid  = threadIdx.x;
    const int lane = tid & 31;
    const int wid  = tid >> 5;
    const int ug   = blockIdx.x >> 1;
    const int bg   = blockIdx.x & 1;
    const int u0   = ug * 8;
    const int b0   = bg * 32;
    unsigned int* cnt = &g_arrive2[bg * 32];

    // ---- stage weights, k-major transposed, unit pairs adjacent ----
    for (int rr = 0; rr < 72; ++rr) {
        int m = rr / 24, r = rr % 24;          // r = g*8 + u
        int g = r >> 3, u = r & 7;
        const float* src;
        if      (m == 0) src = Whh0 + (size_t)(g * 512 + u0 + u) * 512;
        else if (m == 1) src = Wih1 + (size_t)(g * 512 + u0 + u) * 512;
        else             src = Whh1 + (size_t)(g * 512 + u0 + u) * 512;
        int p = r >> 1, h = r & 1;
        float* dst = wt2 + (size_t)(m * 12 + p) * 1024 + h;
        for (int k = tid; k < 512; k += NTHR_R) dst[k * 2] = src[k];
    }

    // compute-warp role
    const int wm = wid >> 2;          // matrix 0..2
    const int wq = wid & 3;           // pair group (3 pairs)

    // epilogue role (tid < 256): warp = uu, lane = b
    const int uu = wid;               // valid for tid < 256
    float bh0r = 0, bh0z = 0, bh0n = 0, bi1r = 0, bi1z = 0, bi1n = 0, bh1r = 0, bh1z = 0, bh1n = 0;
    if (tid < 256) {
        bh0r = bhh0[u0 + uu];  bh0z = bhh0[512 + u0 + uu];  bh0n = bhh0[1024 + u0 + uu];
        bi1r = bih1[u0 + uu];  bi1z = bih1[512 + u0 + uu];  bi1n = bih1[1024 + u0 + uu];
        bh1r = bhh1[u0 + uu];  bh1z = bhh1[512 + u0 + uu];  bh1n = bhh1[1024 + u0 + uu];
    }

    const uint32_t hy_base = smem_u32(hy_s);
    const uint32_t hz_base = smem_u32(hz_s);
    __syncthreads();

    unsigned int epoch = 0;
    float yprev = 0.f, zprev = 0.f;

    for (int t = 0; t <= T_; ++t) {
        // ---- stage xp0[t] slice: xps[g][u][b] ----
        if (t < T_ && tid < 192) {
            int g = tid / 64, r2 = tid % 64, b = r2 & 31, q = r2 >> 5;
            float4 v = *(const float4*)(xp0 + ((size_t)t * 64 + b0 + b) * G3H_ + g * 512 + u0 + q * 4);
            xps[(g * 8 + q * 4 + 0) * 32 + b] = v.x;
            xps[(g * 8 + q * 4 + 1) * 32 + b] = v.y;
            xps[(g * 8 + q * 4 + 2) * 32 + b] = v.z;
            xps[(g * 8 + q * 4 + 3) * 32 + b] = v.w;
        }

        ull acc0 = 0ull, acc1 = 0ull, acc2 = 0ull;   // 3 row-pairs

        if (t >= 1) {
            const float* srcY = hgY + (size_t)(((t - 1) & 1) * 2 + bg) * 16384;
            const float* srcZ = hgZ + (size_t)((t & 1) * 2 + bg) * 16384;   // z[t-2]
            const bool doZ = (t >= 2);

            auto issue = [&](int c) {
                uint32_t dy = hy_base + (c & 1) * 16384;
                const float* sy = srcY + c * 4096;
                for (int idx = tid; idx < 1024; idx += NTHR_R)
                    cp_async16(dy + idx * 16, sy + idx * 4);
                if (doZ) {
                    uint32_t dz = hz_base + (c & 1) * 16384;
                    const float* sz = srcZ + c * 4096;
                    for (int idx = tid; idx < 1024; idx += NTHR_R)
                        cp_async16(dz + idx * 16, sz + idx * 4);
                }
                asm volatile("cp.async.commit_group;" ::: "memory");
            };

            auto compute = [&](int c) {
                if (wm == 2 && !doZ) return;
                const float* hb = ((wm == 2) ? hz_s : hy_s) + (c & 1) * 4096;
                const float* wb = wt2 + (size_t)(wm * 12 + wq * 3) * 1024 + (size_t)c * 256;
                #pragma unroll 8
                for (int kk = 0; kk < 128; kk += 2) {
                    float h0 = hb[kk * 32 + lane];
                    float h1 = hb[kk * 32 + 32 + lane];
                    ull hd0 = pack2(h0, h0);
                    ull hd1 = pack2(h1, h1);
                    ulonglong2 w0 = *(const ulonglong2*)(wb + 0 * 1024 + kk * 2);
                    ulonglong2 w1 = *(const ulonglong2*)(wb + 1 * 1024 + kk * 2);
                    ulonglong2 w2 = *(const ulonglong2*)(wb + 2 * 1024 + kk * 2);
                    acc0 = ffma2(hd0, w0.x, acc0);  acc0 = ffma2(hd1, w0.y, acc0);
                    acc1 = ffma2(hd0, w1.x, acc1);  acc1 = ffma2(hd1, w1.y, acc1);
                    acc2 = ffma2(hd0, w2.x, acc2);  acc2 = ffma2(hd1, w2.y, acc2);
                }
            };

            issue(0);
            issue(1);
            asm volatile("cp.async.wait_group 1;" ::: "memory");
            __syncthreads();
            compute(0);
            __syncthreads();
            issue(2);
            asm volatile("cp.async.wait_group 1;" ::: "memory");
            __syncthreads();
            compute(1);
            __syncthreads();
            issue(3);
            asm volatile("cp.async.wait_group 1;" ::: "memory");
            __syncthreads();
            compute(2);
            asm volatile("cp.async.wait_group 0;" ::: "memory");
            __syncthreads();
            compute(3);
        }

        // ---- dump accumulators: red[(m*12+p)][b] as ull (pair of rows) ----
        {
            ull* rp = red + (size_t)(wm * 12 + wq * 3) * 32 + lane;
            rp[0]  = acc0;
            rp[32] = acc1;
            rp[64] = acc2;
        }
        __syncthreads();

        // ---- epilogue: thread (b=lane, uu=wid), tid < 256 ----
        if (tid < 256) {
            const float* redf = (const float*)red;
            float g0[3], g1[3], g2[3];
            #pragma unroll
            for (int g = 0; g < 3; ++g) {
                int r = g * 8 + uu;
                int p = r >> 1, h = r & 1;
                g0[g] = redf[((0 * 12 + p) * 32 + lane) * 2 + h];
                g1[g] = redf[((1 * 12 + p) * 32 + lane) * 2 + h];
                g2[g] = redf[((2 * 12 + p) * 32 + lane) * 2 + h];
            }

            if (t < T_) {   // layer-0 update -> y[t]
                float xr = xps[(0 * 8 + uu) * 32 + lane];
                float xz = xps[(1 * 8 + uu) * 32 + lane];
                float xn = xps[(2 * 8 + uu) * 32 + lane];
                float r = 1.f / (1.f + __expf(-(xr + g0[0] + bh0r)));
                float z = 1.f / (1.f + __expf(-(xz + g0[1] + bh0z)));
                float n = tanhf(xn + r * (g0[2] + bh0n));
                yprev = (1.f - z) * n + z * yprev;
                hgY[(size_t)((t & 1) * 2 + bg) * 16384 + (u0 + uu) * 32 + lane] = yprev;
            }

            if (t >= 1) {   // layer-1 update -> z[t-1]
                float xinr = g1[0] + bi1r;
                float xinz = g1[1] + bi1z;
                float xinn = g1[2] + bi1n;
                float r = 1.f / (1.f + __expf(-(xinr + g2[0] + bh1r)));
                float z = 1.f / (1.f + __expf(-(xinz + g2[1] + bh1z)));
                float n = tanhf(xinn + r * (g2[2] + bh1n));
                zprev = (1.f - z) * n + z * zprev;
                hgZ[(size_t)(((t - 1) & 1) * 2 + bg) * 16384 + (u0 + uu) * 32 + lane] = zprev;

                // batch partial-mean (full-warp shuffle over b)
                float s = zprev;
                s += __shfl_down_sync(0xffffffffu, s, 16);
                s += __shfl_down_sync(0xffffffffu, s, 8);
                s += __shfl_down_sync(0xffffffffu, s, 4);
                s += __shfl_down_sync(0xffffffffu, s, 2);
                s += __shfl_down_sync(0xffffffffu, s, 1);
                if (lane == 0)
                    pooledp[(size_t)bg * T_ * 512 + (size_t)(t - 1) * 512 + u0 + uu] = s;
            }
        }

        if (t < T_) group_barrier(&epoch, cnt);
    }
}

// ---------------- final FC: combine 2 pooled partials + project ----------------
__global__ void fc_kernel(const float* __restrict__ pooledp, const float* __restrict__ fcW,
                          const float* __restrict__ fcb, float* __restrict__ out)
{
    int t    = blockIdx.x;
    int lane = threadIdx.x;
    float acc[L_];
    #pragma unroll
    for (int l = 0; l < L_; ++l) acc[l] = 0.f;
    for (int k = lane; k < 512; k += 32) {
        float p = pooledp[0 * T_ * 512 + t * 512 + k]
                + pooledp[1 * T_ * 512 + t * 512 + k];
        p *= (1.0f / 64.0f);
        #pragma unroll
        for (int l = 0; l < L_; ++l) acc[l] = fmaf(p, fcW[l * 512 + k], acc[l]);
    }
    #pragma unroll
    for (int l = 0; l < L_; ++l) {
        #pragma unroll
        for (int off = 16; off > 0; off >>= 1)
            acc[l] += __shfl_down_sync(0xffffffffu, acc[l], off);
    }
    if (lane == 0) {
        #pragma unroll
        for (int l = 0; l < L_; ++l) out[t * L_ + l] = acc[l] + fcb[l];
    }
}

// ---------------- launch ----------------
extern "C" void kernel_launch(void* const* d_in, const int* in_sizes, int n_in,
                              void* d_out, int out_size)
{
    const int*   texts = (const int*)  d_in[0];
    const float* emb   = (const float*)d_in[1];
    const float* Wih0  = (const float*)d_in[2];
    const float* Whh0  = (const float*)d_in[3];
    const float* bih0  = (const float*)d_in[4];
    const float* bhh0  = (const float*)d_in[5];
    const float* Wih1  = (const float*)d_in[6];
    const float* Whh1  = (const float*)d_in[7];
    const float* bih1  = (const float*)d_in[8];
    const float* bhh1  = (const float*)d_in[9];
    const float* fcW   = (const float*)d_in[10];
    const float* fcb   = (const float*)d_in[11];
    float* out = (float*)d_out;

    float *xp0, *hgY, *hgZ, *pooledp;
    cudaGetSymbolAddress((void**)&xp0,     g_xp0);
    cudaGetSymbolAddress((void**)&hgY,     g_hgY);
    cudaGetSymbolAddress((void**)&hgZ,     g_hgZ);
    cudaGetSymbolAddress((void**)&pooledp, g_pooledp);

    static bool attr_set = false;
    if (!attr_set) {
        cudaFuncSetAttribute(fused_gru_kernel,
                             cudaFuncAttributeMaxDynamicSharedMemorySize, RS_TOTAL);
        attr_set = true;
    }

    const int M = T_ * B_;                  // 32768
    dim3 ggrid(G3H_ / 64, M / 128);         // (24, 256)

    // layer 0 input projection (embedding gather fused): xp0 = emb[texts] @ Wih0^T + bih0
    gemm_kernel<<<ggrid, 256>>>(emb, texts, Wih0, bih0, xp0, M, G3H_, E_);

    // fused two-layer GRU wavefront (replaces L0-rec, GEMM2, L1-rec)
    init_kernel<<<1, 64>>>();
    fused_gru_kernel<<<NBLK, NTHR_R, RS_TOTAL>>>(
        xp0, Whh0, bhh0, Wih1, bih1, Whh1, bhh1, hgY, hgZ, pooledp);

    // final projection
    fc_kernel<<<T_, 32>>>(pooledp, fcW, fcb, out);
}